// round 1
// baseline (speedup 1.0000x reference)
#include <cuda_runtime.h>
#include <math.h>

#define NLEV 16

struct LevelParams {
    int          R[NLEV];
    unsigned int H[NLEV];
    int          O[NLEV];
    int          linear[NLEV];
};

__global__ void __launch_bounds__(256) grid_fused_kernel(
    const float* __restrict__ xyz,
    const float* __restrict__ bound,
    const float* __restrict__ table,
    const float* __restrict__ w1,
    const float* __restrict__ w2,
    float* __restrict__ out,
    LevelParams lev, int N)
{
    __shared__ __align__(16) float w1s[64][32];  // w1s[j][i] = w1[i][j]
    __shared__ __align__(16) float w2s[64][8];

    const int tid = threadIdx.x;
    for (int i = tid; i < 64 * 32; i += 256) {
        int r = i >> 6, c = i & 63;              // w1 is [32,64] row-major
        w1s[c][r] = w1[i];
    }
    for (int i = tid; i < 64 * 8; i += 256) {
        w2s[i >> 3][i & 7] = w2[i];
    }
    __syncthreads();

    int gt = blockIdx.x * 256 + tid;
    int p  = gt >> 3;
    int oc = gt & 7;          // lanes 0..7 of a group = the 8 outer corners of one point
    if (p >= N) return;

    const float b     = bound[0];
    const float inv2b = 1.0f / (2.0f * b);

    float cx = (xyz[3 * p + 0] + b) * inv2b * 512.0f;
    float cy = (xyz[3 * p + 1] + b) * inv2b * 512.0f;
    float cz = (xyz[3 * p + 2] + b) * inv2b * 512.0f;

    int c0x = min(max((int)floorf(cx), 0), 511);
    int c0y = min(max((int)floorf(cy), 0), 511);
    int c0z = min(max((int)floorf(cz), 0), 511);

    float u = cx - (float)c0x;
    float v = cy - (float)c0y;
    float w = cz - (float)c0z;

    // CORNERS order: index bit2 -> dim0(x), bit1 -> dim1(y), bit0 -> dim2(z)
    int ox = (oc >> 2) & 1, oy = (oc >> 1) & 1, oz = oc & 1;
    float wt = (ox ? u : 1.0f - u) * (oy ? v : 1.0f - v) * (oz ? w : 1.0f - w);

    // encode-point coordinates (exact: integer/512)
    float ex = (float)(c0x + ox) * (1.0f / 512.0f);
    float ey = (float)(c0y + oy) * (1.0f / 512.0f);
    float ez = (float)(c0z + oz) * (1.0f / 512.0f);

    float feats[32];

    #pragma unroll
    for (int l = 0; l < NLEV; l++) {
        const float Rf = (float)lev.R[l];
        float px = ex * Rf + 0.5f;   // ex*R exact (k*R < 2^24), so rounding-free
        float py = ey * Rf + 0.5f;
        float pz = ez * Rf + 0.5f;
        float pgx = floorf(px), pgy = floorf(py), pgz = floorf(pz);
        float fx = px - pgx, fy = py - pgy, fz = pz - pgz;
        int ix = (int)pgx, iy = (int)pgy, iz = (int)pgz;

        float wx0 = 1.0f - fx;
        float wy0 = 1.0f - fy, wz0 = 1.0f - fz;
        float wyz00 = wy0 * wz0, wyz01 = wy0 * fz, wyz10 = fy * wz0, wyz11 = fy * fz;

        const int O = lev.O[l];
        const unsigned H = lev.H[l];
        const float2* tab = reinterpret_cast<const float2*>(table) + O;

        float a0 = 0.0f, a1 = 0.0f;

        if (lev.linear[l]) {
            int s = lev.R[l] + 1, s2 = s * s;
            int base = ix + iy * s + iz * s2;
            #pragma unroll
            for (int dx = 0; dx < 2; dx++) {
                float wxd = dx ? fx : wx0;
                #pragma unroll
                for (int dy = 0; dy < 2; dy++) {
                    #pragma unroll
                    for (int dz = 0; dz < 2; dz++) {
                        int idx = base + dx + dy * s + dz * s2;
                        if (idx >= (int)H) idx -= (int)H;   // idx < 2H provable
                        float2 t = __ldg(&tab[idx]);
                        float wgt = wxd * (dy ? (dz ? wyz11 : wyz10)
                                              : (dz ? wyz01 : wyz00));
                        a0 = fmaf(wgt, t.x, a0);
                        a1 = fmaf(wgt, t.y, a1);
                    }
                }
            }
        } else {
            // hashed level: H == 2^19 by construction -> AND mask
            unsigned mask = H - 1u;
            unsigned hx0 = (unsigned)ix,               hx1 = hx0 + 1u;
            unsigned hy0 = (unsigned)iy * 2654435761u, hy1 = hy0 + 2654435761u;
            unsigned hz0 = (unsigned)iz * 805459861u,  hz1 = hz0 + 805459861u;
            #pragma unroll
            for (int dx = 0; dx < 2; dx++) {
                float wxd = dx ? fx : wx0;
                unsigned hx = dx ? hx1 : hx0;
                #pragma unroll
                for (int dy = 0; dy < 2; dy++) {
                    unsigned hxy = hx ^ (dy ? hy1 : hy0);
                    #pragma unroll
                    for (int dz = 0; dz < 2; dz++) {
                        unsigned idx = (hxy ^ (dz ? hz1 : hz0)) & mask;
                        float2 t = __ldg(&tab[idx]);
                        float wgt = wxd * (dy ? (dz ? wyz11 : wyz10)
                                              : (dz ? wyz01 : wyz00));
                        a0 = fmaf(wgt, t.x, a0);
                        a1 = fmaf(wgt, t.y, a1);
                    }
                }
            }
        }
        feats[2 * l]     = a0;
        feats[2 * l + 1] = a1;
    }

    // ---- MLP: out = (relu(feats @ w1) @ w2) * wt ----
    float acc[8];
    #pragma unroll
    for (int k = 0; k < 8; k++) acc[k] = 0.0f;

    #pragma unroll 4
    for (int j = 0; j < 64; j++) {
        const float4* wr = reinterpret_cast<const float4*>(&w1s[j][0]);
        float h0 = 0.f, h1 = 0.f, h2 = 0.f, h3 = 0.f;
        #pragma unroll
        for (int q = 0; q < 8; q++) {
            float4 wv = wr[q];
            h0 = fmaf(feats[4 * q + 0], wv.x, h0);
            h1 = fmaf(feats[4 * q + 1], wv.y, h1);
            h2 = fmaf(feats[4 * q + 2], wv.z, h2);
            h3 = fmaf(feats[4 * q + 3], wv.w, h3);
        }
        float h = fmaxf((h0 + h1) + (h2 + h3), 0.0f) * wt;
        float4 wa = *reinterpret_cast<const float4*>(&w2s[j][0]);
        float4 wb = *reinterpret_cast<const float4*>(&w2s[j][4]);
        acc[0] = fmaf(h, wa.x, acc[0]); acc[1] = fmaf(h, wa.y, acc[1]);
        acc[2] = fmaf(h, wa.z, acc[2]); acc[3] = fmaf(h, wa.w, acc[3]);
        acc[4] = fmaf(h, wb.x, acc[4]); acc[5] = fmaf(h, wb.y, acc[5]);
        acc[6] = fmaf(h, wb.z, acc[6]); acc[7] = fmaf(h, wb.w, acc[7]);
    }

    // ---- reduce the 8 outer-corner contributions across the 8-lane group ----
    #pragma unroll
    for (int k = 0; k < 8; k++) {
        acc[k] += __shfl_xor_sync(0xffffffffu, acc[k], 1);
        acc[k] += __shfl_xor_sync(0xffffffffu, acc[k], 2);
        acc[k] += __shfl_xor_sync(0xffffffffu, acc[k], 4);
    }
    // every lane now holds all 8 sums; lane oc writes element oc -> out[gt] coalesced
    float t0 = (oc & 1) ? acc[1] : acc[0];
    float t1 = (oc & 1) ? acc[3] : acc[2];
    float t2 = (oc & 1) ? acc[5] : acc[4];
    float t3 = (oc & 1) ? acc[7] : acc[6];
    float u0 = (oc & 2) ? t1 : t0;
    float u1 = (oc & 2) ? t3 : t2;
    float vv = (oc & 4) ? u1 : u0;
    out[gt] = vv;
}

extern "C" void kernel_launch(void* const* d_in, const int* in_sizes, int n_in,
                              void* d_out, int out_size)
{
    const float* xyz   = (const float*)d_in[0];
    const float* bound = (const float*)d_in[1];
    const float* table = (const float*)d_in[2];
    const float* w1    = (const float*)d_in[3];
    const float* w2    = (const float*)d_in[4];
    float* out = (float*)d_out;

    int N = in_sizes[0] / 3;

    // Replicate torch-ngp level construction with the exact numpy double math
    // (same glibc exp2/log2/pow on this host).
    LevelParams lev;
    double scale = exp2(log2(513.0 / 16.0) / 15.0);
    long long off = 0;
    for (int i = 0; i < NLEV; i++) {
        int res = (int)ceil(16.0 * pow(scale, (double)i));
        long long cube = (long long)(res + 1) * (res + 1) * (res + 1);
        long long n = cube;
        if (n > (1LL << 19)) n = (1LL << 19);
        n = ((n + 7) / 8) * 8;
        lev.R[i] = res;
        lev.H[i] = (unsigned)n;
        lev.O[i] = (int)off;
        lev.linear[i] = (cube <= n) ? 1 : 0;
        off += n;
    }

    int total_threads = N * 8;
    int blocks = (total_threads + 255) / 256;
    grid_fused_kernel<<<blocks, 256>>>(xyz, bound, table, w1, w2, out, lev, N);
}